// round 16
// baseline (speedup 1.0000x reference)
#include <cuda_runtime.h>
#include <cstdint>

// Problem constants
#define B 32
#define L 6
#define R 8
#define H 64
#define NTRAJ 262144              // R^L
#define F4_PER_B 393216           // NTRAJ * L / 4
#define TRAJ_PER_BLK 4096
#define F4_PER_BLK   6144         // TRAJ_PER_BLK * 6 / 4
#define NPROD 192                 // producer blocks, 8 items each -> 1536
#define PROD_PER_BATCH 6
#define CONS_PER_BATCH 64
#define GRID_BLKS 2048
#define SYNC_STRIDE 64            // ints -> 256 B between sync slots

// Device state (zero-initialized; per-batch reset at end of each launch)
__device__ float g_q0[B * L * R];
__device__ int   g_cnt[B * SYNC_STRIDE];   // producer-arrival counters
__device__ int   g_fin[B * SYNC_STRIDE];   // consumer-finish counters

// ---------------------------------------------------------------------------
// Fused kernel (final, = R13 best-measured config).
//   All 2048 blocks expand one tile (b = bid>>6, xb = bid&63).
//   Blocks 0..191 first produce: block p computes items 8p..8p+7 (8 items x
//   64 lanes, one round), one contention-free red.release per producer on the
//   batch's counter (256 B apart). Consumers acquire-poll (tid 0), load q0,
//   then run the clean, uninterrupted store stream (96 KB coalesced float4
//   streaming stores — the HBM-write-roofline body). Replay reset at the
//   tail, per-batch staggered.
// ---------------------------------------------------------------------------
__global__ void __launch_bounds__(512) zdec_fused_kernel(
    const float* __restrict__ phi,   // (B, L)
    const float* __restrict__ rp,    // (L, R, 1)
    const float* __restrict__ W1,    // (H, 2)
    const float* __restrict__ b1,
    const float* __restrict__ W2,    // (H, H)
    const float* __restrict__ b2,
    const float* __restrict__ W3,    // (OUT, H) — row 0 only
    const float* __restrict__ b3,
    float* __restrict__ out)
{
    __shared__ union {
        struct {
            float w2[H * 65];
            float h1[8][H];
            float red[8][2];
        } p;
        float sq[L * R];
    } sm;

    const int bid = blockIdx.x;
    const int tid = threadIdx.x;

    // ---------------- producer phase (blocks 0..191) ----------------------
    if (bid < NPROD) {
        const int item = tid >> 6;          // 0..7
        const int j    = tid & 63;          // hidden lane
        const int gi   = bid * 8 + item;    // item 0..1535 (batch = bid/6)
        const int pb   = bid / PROD_PER_BATCH;
        const int lr   = gi - pb * (L * R);
        const int l    = lr >> 3;

        // stage W2 via float4 (coalesced), 65-pitch conflict-free layout
#pragma unroll
        for (int t = tid; t < (H * H) / 4; t += 512) {
            const float4 w = reinterpret_cast<const float4*>(W2)[t];
            const int base = t * 4;
            float* d = &sm.p.w2[(base >> 6) * 65 + (base & 63)];
            d[0] = w.x; d[1] = w.y; d[2] = w.z; d[3] = w.w;
        }

        const float2 w1   = reinterpret_cast<const float2*>(W1)[j];
        const float  x    = rp[lr];
        const float  pphi = phi[pb * L + l];
        const float  h1v  = fmaxf(fmaf(w1.x, x, fmaf(w1.y, pphi, b1[j])), 0.0f);
        __syncthreads();

        sm.p.h1[item][j] = h1v;
        __syncthreads();

        float acc = b2[j];
#pragma unroll
        for (int k = 0; k < H; k++)
            acc = fmaf(sm.p.w2[j * 65 + k], sm.p.h1[item][k], acc);

        float q = W3[j] * fmaxf(acc, 0.0f);
#pragma unroll
        for (int off = 16; off > 0; off >>= 1)
            q += __shfl_xor_sync(0xffffffffu, q, off);
        if ((j & 31) == 0) sm.p.red[item][j >> 5] = q;
        __syncthreads();
        if (j == 0)
            g_q0[gi] = sm.p.red[item][0] + sm.p.red[item][1] + b3[0];

        // order g_q0 stores (all block threads) before the release-add
        __syncthreads();
        if (tid == 0)
            asm volatile("red.release.gpu.global.add.u32 [%0], %1;"
                         :: "l"(&g_cnt[pb * SYNC_STRIDE]), "r"(1) : "memory");
    }

    // ---------------- consumer phase (all blocks) --------------------------
    const int b  = bid >> 6;                // batch   (slow — proven locality)
    const int xb = bid & 63;                // tile

    if (tid == 0) {
        int c;
        do {
            asm volatile("ld.acquire.gpu.global.u32 %0, [%1];"
                         : "=r"(c) : "l"(&g_cnt[b * SYNC_STRIDE]) : "memory");
            if (c < PROD_PER_BATCH) __nanosleep(32);
        } while (c < PROD_PER_BATCH);
    }
    __syncthreads();

    if (tid < L * R)
        sm.sq[tid] = g_q0[b * (L * R) + tid];
    __syncthreads();

    const int n_blk = xb * TRAJ_PER_BLK;
    float4* op = reinterpret_cast<float4*>(out)
               + (size_t)b * F4_PER_B + (size_t)xb * F4_PER_BLK;

#pragma unroll
    for (int it = 0; it < F4_PER_BLK / 512; it++) {
        const int jl_blk = it * 512 + tid;
        const int ch  = jl_blk / 768;
        const int jl  = jl_blk - ch * 768;             // 0..767 within chunk
        const int nc  = n_blk + ch * 512;
        const float c3 = sm.sq[24 + ((nc >> 9)  & 7)];
        const float c4 = sm.sq[32 + ((nc >> 12) & 7)];
        const float c5 = sm.sq[40 + ((nc >> 15) & 7)];

        const int n   = (2 * jl) / 3;                  // local traj 0..511
        const int pat = jl % 3;
        const int d0 = n & 7;
        const int d1 = (n >> 3) & 7;
        const int d2 = (n >> 6) & 7;

        float4 v;
        if (pat == 0) {
            v.x = sm.sq[d0];  v.y = sm.sq[8 + d1];  v.z = sm.sq[16 + d2];  v.w = c3;
        } else if (pat == 1) {
            v.x = c4;  v.y = c5;  v.z = sm.sq[d0 + 1];  v.w = sm.sq[8 + d1];
        } else {
            v.x = sm.sq[16 + d2];  v.y = c3;  v.z = c4;  v.w = c5;
        }
        __stcs(op + jl_blk, v);
    }

    // ---------------- replay reset (tail, per-batch, staggered) ------------
    __syncthreads();
    if (tid == 0) {
        const int old = atomicAdd(&g_fin[b * SYNC_STRIDE], 1);
        if (old == CONS_PER_BATCH - 1) {
            g_cnt[b * SYNC_STRIDE] = 0;
            g_fin[b * SYNC_STRIDE] = 0;
            __threadfence();
        }
    }
}

// ---------------------------------------------------------------------------
extern "C" void kernel_launch(void* const* d_in, const int* in_sizes, int n_in,
                              void* d_out, int out_size)
{
    const float* phi = (const float*)d_in[0];
    const float* rp  = (const float*)d_in[1];
    const float* W1  = (const float*)d_in[2];
    const float* b1  = (const float*)d_in[3];
    const float* W2  = (const float*)d_in[4];
    const float* b2  = (const float*)d_in[5];
    const float* W3  = (const float*)d_in[6];
    const float* b3  = (const float*)d_in[7];
    float* out = (float*)d_out;

    zdec_fused_kernel<<<GRID_BLKS, 512>>>(phi, rp, W1, b1, W2, b2, W3, b3, out);
}

// round 17
// speedup vs baseline: 1.0323x; 1.0323x over previous
#include <cuda_runtime.h>
#include <cstdint>

// Problem constants
#define B 32
#define L 6
#define R 8
#define H 64
#define NTRAJ 262144              // R^L
#define F4_PER_B 393216           // NTRAJ * L / 4
#define TRAJ_PER_BLK 4096
#define F4_PER_BLK   6144         // TRAJ_PER_BLK * 6 / 4
#define ITEMS_PER_MLP_BLK 4

// Scratch for the 1536 MLP outputs q0[b][l][r]
__device__ float g_q0[B * L * R];

// ---------------------------------------------------------------------------
// Kernel 1: tiny MLP, 4 items per 256-thread block (best-measured config).
// W2 staged coalesced into shared with 65-float pitch -> conflict-free
// compute reads (bank of sW2[j*65+k] = (j+k)%32, distinct across lanes).
// ---------------------------------------------------------------------------
__global__ void __launch_bounds__(256) zdec_mlp_kernel(
    const float* __restrict__ phi,   // (B, L)
    const float* __restrict__ rp,    // (L, R, 1)
    const float* __restrict__ W1,    // (H, 2)
    const float* __restrict__ b1,
    const float* __restrict__ W2,    // (H, H)
    const float* __restrict__ b2,
    const float* __restrict__ W3,    // (OUT, H) — row 0 only
    const float* __restrict__ b3)
{
    __shared__ float sW2[H * 65];
    __shared__ float sh1[ITEMS_PER_MLP_BLK][H];
    __shared__ float sred[ITEMS_PER_MLP_BLK][2];

    const int tid  = threadIdx.x;
    const int item = tid >> 6;          // 0..3
    const int j    = tid & 63;          // hidden index

    // coalesced W2 stage: thread t loads W2[t], W2[t+256], ...
#pragma unroll
    for (int t = tid; t < H * H; t += 256) {
        const int g = t >> 6, k = t & 63;
        sW2[g * 65 + k] = W2[t];
    }

    const int ii = blockIdx.x * ITEMS_PER_MLP_BLK + item;   // 0..1535
    const int b  = ii / (L * R);
    const int lr = ii % (L * R);
    const int l  = lr / R;

    const float  x  = rp[lr];
    const float  p  = phi[b * L + l];
    const float2 w1 = reinterpret_cast<const float2*>(W1)[j];

    sh1[item][j] = fmaxf(fmaf(w1.x, x, fmaf(w1.y, p, b1[j])), 0.0f);
    __syncthreads();

    float acc = b2[j];
#pragma unroll
    for (int k = 0; k < H; k++)
        acc = fmaf(sW2[j * 65 + k], sh1[item][k], acc);

    float q = W3[j] * fmaxf(acc, 0.0f);
#pragma unroll
    for (int off = 16; off > 0; off >>= 1)
        q += __shfl_xor_sync(0xffffffffu, q, off);
    if ((j & 31) == 0) sred[item][j >> 5] = q;
    __syncthreads();
    if (j == 0)
        g_q0[ii] = sred[item][0] + sred[item][1] + b3[0];
}

// ---------------------------------------------------------------------------
// Kernel 2: expansion. out[b][n][l] = q0[b][l][(n >> 3l) & 7].
// Block = (bx, b): 4096 trajectories = 6144 coalesced float4s, in 8 chunks of
// 512 traj; within a chunk digits l=3,4,5 are constants (c3,c4,c5).
// Streaming stores (__stcs): output is write-once.
// This body is at the DRAM-write roofline (~201 MB / ~5.7 TB/s sustained);
// verified invariant across STG-256/STG-512/TMA-bulk and 4 schedules.
// ---------------------------------------------------------------------------
__global__ void __launch_bounds__(512) zdec_expand_kernel(float* __restrict__ out)
{
    __shared__ float sq[L * R];          // 48 values, layout l*8 + digit

    const int tid = threadIdx.x;
    const int b   = blockIdx.y;
    if (tid < L * R)
        sq[tid] = g_q0[b * (L * R) + tid];
    __syncthreads();

    const int n_blk = blockIdx.x * TRAJ_PER_BLK;
    float4* op = reinterpret_cast<float4*>(out)
               + (size_t)b * F4_PER_B + (size_t)blockIdx.x * F4_PER_BLK;

#pragma unroll
    for (int it = 0; it < F4_PER_BLK / 512; it++) {
        const int jl_blk = it * 512 + tid;
        const int ch  = jl_blk / 768;
        const int jl  = jl_blk - ch * 768;             // 0..767 within chunk
        const int nc  = n_blk + ch * 512;
        const float c3 = sq[24 + ((nc >> 9)  & 7)];
        const float c4 = sq[32 + ((nc >> 12) & 7)];
        const float c5 = sq[40 + ((nc >> 15) & 7)];

        const int n   = (2 * jl) / 3;                  // local traj 0..511
        const int pat = jl % 3;
        const int d0 = n & 7;
        const int d1 = (n >> 3) & 7;
        const int d2 = (n >> 6) & 7;

        float4 v;
        if (pat == 0) {
            v.x = sq[d0];  v.y = sq[8 + d1];  v.z = sq[16 + d2];  v.w = c3;
        } else if (pat == 1) {
            v.x = c4;  v.y = c5;  v.z = sq[d0 + 1];  v.w = sq[8 + d1];
        } else {
            v.x = sq[16 + d2];  v.y = c3;  v.z = c4;  v.w = c5;
        }
        __stcs(op + jl_blk, v);
    }
}

// ---------------------------------------------------------------------------
extern "C" void kernel_launch(void* const* d_in, const int* in_sizes, int n_in,
                              void* d_out, int out_size)
{
    const float* phi = (const float*)d_in[0];
    const float* rp  = (const float*)d_in[1];
    const float* W1  = (const float*)d_in[2];
    const float* b1  = (const float*)d_in[3];
    const float* W2  = (const float*)d_in[4];
    const float* b2  = (const float*)d_in[5];
    const float* W3  = (const float*)d_in[6];
    const float* b3  = (const float*)d_in[7];
    float* out = (float*)d_out;

    zdec_mlp_kernel<<<(B * L * R) / ITEMS_PER_MLP_BLK, 256>>>(
        phi, rp, W1, b1, W2, b2, W3, b3);

    dim3 grid(NTRAJ / TRAJ_PER_BLK, B);                // (64, 32)
    zdec_expand_kernel<<<grid, 512>>>(out);
}